// round 4
// baseline (speedup 1.0000x reference)
#include <cuda_runtime.h>
#include <math.h>

typedef unsigned long long u64;

#define THREADS 256
#define LP_BLOCKS 1024
#define MAXB 2097152

// ---------------- encoder smem layout (float offsets) ----------------
#define EW1   0          // 22 x 64
#define EB1   1408
#define ELN1G 1472
#define ELN1B 1536
#define EW2   1600       // 64 x 64
#define EB2   5696
#define ELN2G 5760
#define ELN2B 5824
#define EW3   5888       // 64 x 32
#define EB3   7936       // 32
#define ESTA  7968       // 256 x 68 stash (row A)
#define ESTB  25376      // 256 x 68 stash (row B)
#define ENC_SM (25376 + 17408)

// ---------------- flow smem layout (float offsets) ----------------
#define FW1   0          // 33 x 64
#define FB1   2112
#define FW2   2176       // 64 x 64
#define FB2   6272
#define FW3   6336       // 64 x 24 (padded 23->24)
#define FB3   7872       // 24 (padded)
#define FSTA  7904       // 256 x 68
#define FSTB  25312      // 256 x 68
#define FLOW_SM (25312 + 17408)

__device__ float g_z[MAXB];
__device__ float g_ladj[MAXB];
__device__ float g_block_sums[LP_BLOCKS];

// ---------------- packed f32x2 helpers ----------------
__device__ __forceinline__ u64 bcast2(float x) {
    u64 r;
    asm("mov.b64 %0, {%1, %1};" : "=l"(r) : "f"(x));
    return r;
}
__device__ __forceinline__ void fma2(u64& acc, u64 a, u64 b) {
    asm("fma.rn.f32x2 %0, %1, %2, %0;" : "+l"(acc) : "l"(a), "l"(b));
}
__device__ __forceinline__ void unpack2(u64 v, float& lo, float& hi) {
    asm("mov.b64 {%0, %1}, %2;" : "=f"(lo), "=f"(hi) : "l"(v));
}

// Two-row GEMV: one broadcast weight load feeds both rows (RB=2).
// out[2*NPAIR] = a[NIN] @ W[NIN][2*NPAIR] + bias, optional ReLU.
template<int NIN, int NPAIR, int CP, bool RELU>
__device__ __forceinline__ void gemv_rb2(
    const float* __restrict__ aA, const float* __restrict__ aB,
    const float* __restrict__ W,  const float* __restrict__ bias,
    float* __restrict__ outA, float* __restrict__ outB)
{
#pragma unroll
    for (int c0 = 0; c0 < NPAIR; c0 += CP) {
        u64 accA[CP], accB[CP];
        const ulonglong2* bp =
            reinterpret_cast<const ulonglong2*>(bias + 2 * c0);
#pragma unroll
        for (int q = 0; q < CP / 2; q++) {
            ulonglong2 b2 = bp[q];
            accA[2 * q] = b2.x; accA[2 * q + 1] = b2.y;
            accB[2 * q] = b2.x; accB[2 * q + 1] = b2.y;
        }
#pragma unroll
        for (int i = 0; i < NIN; i++) {
            u64 aa = bcast2(aA[i]);
            u64 ab = bcast2(aB[i]);
            const ulonglong2* wp =
                reinterpret_cast<const ulonglong2*>(W + i * (2 * NPAIR) + 2 * c0);
#pragma unroll
            for (int q = 0; q < CP / 2; q++) {
                ulonglong2 w2 = wp[q];
                fma2(accA[2 * q],     aa, w2.x);
                fma2(accA[2 * q + 1], aa, w2.y);
                fma2(accB[2 * q],     ab, w2.x);
                fma2(accB[2 * q + 1], ab, w2.y);
            }
        }
#pragma unroll
        for (int p = 0; p < CP; p++) {
            float lo, hi;
            unpack2(accA[p], lo, hi);
            if (RELU) { lo = fmaxf(lo, 0.f); hi = fmaxf(hi, 0.f); }
            outA[2 * (c0 + p)] = lo; outA[2 * (c0 + p) + 1] = hi;
            unpack2(accB[p], lo, hi);
            if (RELU) { lo = fmaxf(lo, 0.f); hi = fmaxf(hi, 0.f); }
            outB[2 * (c0 + p)] = lo; outB[2 * (c0 + p) + 1] = hi;
        }
    }
}

__device__ __forceinline__ void load64(float* __restrict__ dst,
                                       const float* __restrict__ st) {
#pragma unroll
    for (int q = 0; q < 16; q++) {
        float4 v = reinterpret_cast<const float4*>(st)[q];
        dst[4 * q] = v.x; dst[4 * q + 1] = v.y;
        dst[4 * q + 2] = v.z; dst[4 * q + 3] = v.w;
    }
}

__device__ __forceinline__ void ln_gelu(float* h, const float* __restrict__ g,
                                        const float* __restrict__ b) {
    float m0 = 0.f, m1 = 0.f;
#pragma unroll
    for (int j = 0; j < 64; j += 2) { m0 += h[j]; m1 += h[j + 1]; }
    float mu = (m0 + m1) * (1.f / 64.f);
    float v0 = 0.f, v1 = 0.f;
#pragma unroll
    for (int j = 0; j < 64; j += 2) {
        float d0 = h[j] - mu;      v0 = fmaf(d0, d0, v0);
        float d1 = h[j + 1] - mu;  v1 = fmaf(d1, d1, v1);
    }
    float var = (v0 + v1) * (1.f / 64.f);
    float inv = rsqrtf(var + 1e-5f);
#pragma unroll
    for (int j = 0; j < 64; j++) {
        float v = (h[j] - mu) * inv * g[j] + b[j];
        h[j] = 0.5f * v * (1.f + erff(v * 0.70710678118654752f));
    }
}

// ---------------- rational-quadratic spline (one row) ----------------
__device__ __forceinline__ void rqs_step(const float* __restrict__ p3,
                                         float& z, float& ladj) {
    const float* pw = p3;
    const float* ph = p3 + 8;
    const float* pd = p3 + 16;
    float ew[8], eh[8];
    float mw = pw[0], mh = ph[0];
#pragma unroll
    for (int n = 1; n < 8; n++) {
        mw = fmaxf(mw, pw[n]); mh = fmaxf(mh, ph[n]);
    }
    float sw = 0.f, sh = 0.f;
#pragma unroll
    for (int n = 0; n < 8; n++) {
        ew[n] = __expf(pw[n] - mw); sw += ew[n];
        eh[n] = __expf(ph[n] - mh); sh += eh[n];
    }
    float aw = __fdividef(10.0f, sw), ah = __fdividef(10.0f, sh);
    float xk[9], yk[9], dk[9];
    xk[0] = -5.f; yk[0] = -5.f; dk[0] = 1.f; dk[8] = 1.f;
#pragma unroll
    for (int n = 0; n < 8; n++) {
        xk[n + 1] = fmaf(ew[n], aw, xk[n]);
        yk[n + 1] = fmaf(eh[n], ah, yk[n]);
    }
#pragma unroll
    for (int n = 0; n < 7; n++) {
        float v = pd[n];
        dk[n + 1] = fmaxf(v, 0.f) + log1pf(__expf(-fabsf(v)));
    }
    bool inside = (z > -5.f) && (z < 5.f);
    float xc = fminf(fmaxf(z, -5.f), 5.f);
    float x0 = xk[0], x1 = xk[1], y0 = yk[0], y1 = yk[1];
    float d0 = dk[0], d1 = dk[1];
#pragma unroll
    for (int m = 1; m < 8; m++) {
        bool cc = xc >= xk[m];
        x0 = cc ? xk[m] : x0;     x1 = cc ? xk[m + 1] : x1;
        y0 = cc ? yk[m] : y0;     y1 = cc ? yk[m + 1] : y1;
        d0 = cc ? dk[m] : d0;     d1 = cc ? dk[m + 1] : d1;
    }
    float wk = x1 - x0, hk = y1 - y0;
    float s  = __fdividef(hk, wk);
    float xi = __fdividef(xc - x0, wk);
    float om = 1.f - xi;
    float den = fmaf(fmaf(-2.f, s, d0 + d1), xi * om, s);
    float yin = y0 + hk * __fdividef(s * xi * xi + d0 * xi * om, den);
    float A   = fmaf(d1 * xi, xi, fmaf(2.f * s * xi, om, d0 * om * om));
    float ldin = __logf(__fdividef((s * s) * A, den * den));
    z    = inside ? yin : z;
    ladj = inside ? (ladj + ldin) : ladj;
}

__global__ void nudge_kernel(int) {}

// ======================= encoder =======================
__global__ __launch_bounds__(THREADS, 1)
void encoder_kernel(
    const float* __restrict__ metadata, const float* __restrict__ mask,
    const float* __restrict__ eW1, const float* __restrict__ eb1,
    const float* __restrict__ eg1, const float* __restrict__ ebt1,
    const float* __restrict__ eW2, const float* __restrict__ eb2,
    const float* __restrict__ eg2, const float* __restrict__ ebt2,
    const float* __restrict__ eW3, const float* __restrict__ eb3,
    float* __restrict__ out_latent, int B)
{
    extern __shared__ float sm[];
    const int tid = threadIdx.x;
    for (int idx = tid; idx < 22 * 64; idx += THREADS) sm[EW1 + idx] = eW1[idx];
    for (int idx = tid; idx < 64; idx += THREADS) {
        sm[EB1 + idx] = eb1[idx];  sm[ELN1G + idx] = eg1[idx];
        sm[ELN1B + idx] = ebt1[idx];
        sm[EB2 + idx] = eb2[idx];  sm[ELN2G + idx] = eg2[idx];
        sm[ELN2B + idx] = ebt2[idx];
    }
    for (int idx = tid; idx < 64 * 64; idx += THREADS) sm[EW2 + idx] = eW2[idx];
    for (int idx = tid; idx < 64 * 32; idx += THREADS) sm[EW3 + idx] = eW3[idx];
    for (int idx = tid; idx < 32; idx += THREADS)      sm[EB3 + idx] = eb3[idx];
    __syncthreads();

    float* __restrict__ stA = sm + ESTA + tid * 68;
    float* __restrict__ stB = sm + ESTB + tid * 68;

    for (int base = blockIdx.x * (2 * THREADS); base < B;
         base += gridDim.x * (2 * THREADS)) {
        int r0 = base + tid, r1 = base + THREADS + tid;
        bool v0 = r0 < B, v1 = r1 < B;
        float xA[22], xB[22];
#pragma unroll
        for (int i = 0; i < 11; i++) {
            xA[i]      = v0 ? __ldg(metadata + (size_t)r0 * 11 + i) : 0.f;
            xA[11 + i] = v0 ? __ldg(mask + (size_t)r0 * 11 + i) : 0.f;
            xB[i]      = v1 ? __ldg(metadata + (size_t)r1 * 11 + i) : 0.f;
            xB[11 + i] = v1 ? __ldg(mask + (size_t)r1 * 11 + i) : 0.f;
        }
        gemv_rb2<22, 32, 8, false>(xA, xB, sm + EW1, sm + EB1, stA, stB);
        float hA[64], hB[64];
        load64(hA, stA); load64(hB, stB);
        ln_gelu(hA, sm + ELN1G, sm + ELN1B);
        ln_gelu(hB, sm + ELN1G, sm + ELN1B);
        gemv_rb2<64, 32, 8, false>(hA, hB, sm + EW2, sm + EB2, stA, stB);
        float h2A[64], h2B[64];
        load64(h2A, stA); load64(h2B, stB);
        ln_gelu(h2A, sm + ELN2G, sm + ELN2B);
        ln_gelu(h2B, sm + ELN2G, sm + ELN2B);
        gemv_rb2<64, 16, 8, false>(h2A, h2B, sm + EW3, sm + EB3, stA, stB);
        if (v0) {
            float4* o = reinterpret_cast<float4*>(out_latent + (size_t)r0 * 32);
#pragma unroll
            for (int q = 0; q < 8; q++)
                o[q] = reinterpret_cast<const float4*>(stA)[q];
        }
        if (v1) {
            float4* o = reinterpret_cast<float4*>(out_latent + (size_t)r1 * 32);
#pragma unroll
            for (int q = 0; q < 8; q++)
                o[q] = reinterpret_cast<const float4*>(stB)[q];
        }
    }
}

// ======================= one flow transform =======================
__global__ __launch_bounds__(THREADS, 1)
void flow_kernel(
    const float* __restrict__ latent, const float* __restrict__ prot,
    const float* __restrict__ age,
    const float* __restrict__ fW1t, const float* __restrict__ fb1t,
    const float* __restrict__ fW2t, const float* __restrict__ fb2t,
    const float* __restrict__ fW3t, const float* __restrict__ fb3t,
    int first, int B)
{
    extern __shared__ float sm[];
    const int tid = threadIdx.x;
    for (int idx = tid; idx < 33 * 64; idx += THREADS) sm[FW1 + idx] = fW1t[idx];
    for (int idx = tid; idx < 64; idx += THREADS) {
        sm[FB1 + idx] = fb1t[idx];
        sm[FB2 + idx] = fb2t[idx];
    }
    for (int idx = tid; idx < 64 * 64; idx += THREADS) sm[FW2 + idx] = fW2t[idx];
    for (int idx = tid; idx < 64 * 24; idx += THREADS) {
        int i = idx / 24, n = idx % 24;
        sm[FW3 + idx] = (n < 23) ? fW3t[i * 23 + n] : 0.f;
    }
    for (int idx = tid; idx < 24; idx += THREADS)
        sm[FB3 + idx] = (idx < 23) ? fb3t[idx] : 0.f;
    __syncthreads();

    float* __restrict__ stA = sm + FSTA + tid * 68;
    float* __restrict__ stB = sm + FSTB + tid * 68;

    for (int base = blockIdx.x * (2 * THREADS); base < B;
         base += gridDim.x * (2 * THREADS)) {
        int r0 = base + tid, r1 = base + THREADS + tid;
        bool v0 = r0 < B, v1 = r1 < B;

        float cA[33], cB[33];
#pragma unroll
        for (int q = 0; q < 8; q++) {
            float4 a = v0 ? reinterpret_cast<const float4*>(
                                latent + (size_t)r0 * 32)[q]
                          : make_float4(0.f, 0.f, 0.f, 0.f);
            cA[4 * q] = a.x; cA[4 * q + 1] = a.y;
            cA[4 * q + 2] = a.z; cA[4 * q + 3] = a.w;
            float4 b = v1 ? reinterpret_cast<const float4*>(
                                latent + (size_t)r1 * 32)[q]
                          : make_float4(0.f, 0.f, 0.f, 0.f);
            cB[4 * q] = b.x; cB[4 * q + 1] = b.y;
            cB[4 * q + 2] = b.z; cB[4 * q + 3] = b.w;
        }
        cA[32] = v0 ? __ldg(prot + r0) : 0.f;
        cB[32] = v1 ? __ldg(prot + r1) : 0.f;

        float zA = 0.f, zB = 0.f, lA = 0.f, lB = 0.f;
        if (first) {
            zA = v0 ? __ldg(age + r0) : 0.f;
            zB = v1 ? __ldg(age + r1) : 0.f;
        } else {
            zA = v0 ? g_z[r0] : 0.f;     lA = v0 ? g_ladj[r0] : 0.f;
            zB = v1 ? g_z[r1] : 0.f;     lB = v1 ? g_ladj[r1] : 0.f;
        }

        gemv_rb2<33, 32, 8, true>(cA, cB, sm + FW1, sm + FB1, stA, stB);
        float p1A[64], p1B[64];
        load64(p1A, stA); load64(p1B, stB);
        gemv_rb2<64, 32, 8, true>(p1A, p1B, sm + FW2, sm + FB2, stA, stB);
        float p2A[64], p2B[64];
        load64(p2A, stA); load64(p2B, stB);
        float p3A[24], p3B[24];
        gemv_rb2<64, 12, 6, false>(p2A, p2B, sm + FW3, sm + FB3, p3A, p3B);

        rqs_step(p3A, zA, lA);
        rqs_step(p3B, zB, lB);

        if (v0) { g_z[r0] = zA; g_ladj[r0] = lA; }
        if (v1) { g_z[r1] = zB; g_ladj[r1] = lB; }
    }
}

// ======================= log_prob + reduction =======================
__global__ __launch_bounds__(256, 1)
void lp_kernel(float* __restrict__ out_lp, int B) {
    __shared__ float red[256];
    float lsum = 0.f;
    for (int row = blockIdx.x * 256 + threadIdx.x; row < B;
         row += gridDim.x * 256) {
        float z = g_z[row];
        float lp = fmaf(-0.5f, z * z, -0.91893853320467274f) + g_ladj[row];
        out_lp[row] = lp;
        lsum += lp;
    }
    red[threadIdx.x] = lsum;
    __syncthreads();
#pragma unroll
    for (int off = 128; off > 0; off >>= 1) {
        if (threadIdx.x < off) red[threadIdx.x] += red[threadIdx.x + off];
        __syncthreads();
    }
    if (threadIdx.x == 0) g_block_sums[blockIdx.x] = red[0];
}

__global__ void finalize_kernel(int B, float* __restrict__ out_nll) {
    __shared__ double red[256];
    double s = 0.0;
    for (int i = threadIdx.x; i < LP_BLOCKS; i += 256)
        s += (double)g_block_sums[i];
    red[threadIdx.x] = s;
    __syncthreads();
#pragma unroll
    for (int off = 128; off > 0; off >>= 1) {
        if (threadIdx.x < off) red[threadIdx.x] += red[threadIdx.x + off];
        __syncthreads();
    }
    if (threadIdx.x == 0)
        out_nll[0] = (float)(-red[0] / (double)B);
}

extern "C" void kernel_launch(void* const* d_in, const int* in_sizes, int n_in,
                              void* d_out, int out_size) {
    const float* metadata = (const float*)d_in[0];
    const float* prot     = (const float*)d_in[1];
    const float* age      = (const float*)d_in[2];
    const float* mask     = (const float*)d_in[3];
    const float* eW1  = (const float*)d_in[4];
    const float* eb1  = (const float*)d_in[5];
    const float* eg1  = (const float*)d_in[6];
    const float* ebt1 = (const float*)d_in[7];
    const float* eW2  = (const float*)d_in[8];
    const float* eb2  = (const float*)d_in[9];
    const float* eg2  = (const float*)d_in[10];
    const float* ebt2 = (const float*)d_in[11];
    const float* eW3  = (const float*)d_in[12];
    const float* eb3  = (const float*)d_in[13];
    const float* fW1  = (const float*)d_in[14];
    const float* fb1  = (const float*)d_in[15];
    const float* fW2  = (const float*)d_in[16];
    const float* fb2  = (const float*)d_in[17];
    const float* fW3  = (const float*)d_in[18];
    const float* fb3  = (const float*)d_in[19];

    const int B = in_sizes[1];
    float* out = (float*)d_out;
    float* out_latent = out;
    float* out_lp     = out + (size_t)B * 32;
    float* out_nll    = out + (size_t)B * 33;

    int sms = 148;
    cudaDeviceProp prop;
    if (cudaGetDeviceProperties(&prop, 0) == cudaSuccess)
        sms = prop.multiProcessorCount;

    size_t enc_smem  = (size_t)ENC_SM * sizeof(float);
    size_t flow_smem = (size_t)FLOW_SM * sizeof(float);
    cudaFuncSetAttribute(encoder_kernel,
                         cudaFuncAttributeMaxDynamicSharedMemorySize,
                         (int)enc_smem);
    cudaFuncSetAttribute(flow_kernel,
                         cudaFuncAttributeMaxDynamicSharedMemorySize,
                         (int)flow_smem);

    // launch idx map: 0 nudge, 1 enc, 2 f0, 3 f1, 4 f2, 5 f3 (<- ncu -s 5),
    // 6 lp, 7 finalize
    nudge_kernel<<<1, 32>>>(0);

    encoder_kernel<<<sms, THREADS, enc_smem>>>(
        metadata, mask, eW1, eb1, eg1, ebt1, eW2, eb2, eg2, ebt2, eW3, eb3,
        out_latent, B);

    for (int t = 0; t < 4; t++) {
        flow_kernel<<<sms, THREADS, flow_smem>>>(
            out_latent, prot, age,
            fW1 + (size_t)t * 33 * 64, fb1 + (size_t)t * 64,
            fW2 + (size_t)t * 64 * 64, fb2 + (size_t)t * 64,
            fW3 + (size_t)t * 64 * 23, fb3 + (size_t)t * 23,
            (t == 0) ? 1 : 0, B);
    }

    lp_kernel<<<LP_BLOCKS, 256>>>(out_lp, B);
    finalize_kernel<<<1, 256>>>(B, out_nll);
}

// round 5
// speedup vs baseline: 1.0811x; 1.0811x over previous
#include <cuda_runtime.h>
#include <math.h>

typedef unsigned long long u64;

#define THREADS 512
#define LP_BLOCKS 1024
#define MAXB 2097152

// ---------------- encoder smem layout (float offsets) ----------------
#define EW1   0          // 22 x 64
#define EB1   1408
#define ELN1G 1472
#define ELN1B 1536
#define EW2   1600       // 64 x 64
#define EB2   5696
#define ELN2G 5760
#define ELN2B 5824
#define EW3   5888       // 64 x 32
#define EB3   7936       // 32
#define ESTASH 7968      // THREADS x 65 per-thread bounce buffer
#define ENC_SM (7968 + THREADS * 65)

// ---------------- flow smem layout (float offsets) ----------------
#define FW1   0          // 33 x 64
#define FB1   2112
#define FW2   2176       // 64 x 64
#define FB2   6272
#define FW3   6336       // 64 x 24 (out padded 23->24)
#define FB3   7872       // 24 (padded)
#define FSTASH 7904      // THREADS x 65
#define FLOW_SM (7904 + THREADS * 65)

__device__ float g_z[MAXB];
__device__ float g_ladj[MAXB];
__device__ float g_block_sums[LP_BLOCKS];

// ---------------- packed f32x2 helpers ----------------
__device__ __forceinline__ u64 bcast2(float x) {
    u64 r;
    asm("mov.b64 %0, {%1, %1};" : "=l"(r) : "f"(x));
    return r;
}
__device__ __forceinline__ void fma2(u64& acc, u64 a, u64 b) {
    asm("fma.rn.f32x2 %0, %1, %2, %0;" : "+l"(acc) : "l"(a), "l"(b));
}
__device__ __forceinline__ void unpack2(u64 v, float& lo, float& hi) {
    asm("mov.b64 {%0, %1}, %2;" : "=f"(lo), "=f"(hi) : "l"(v));
}

// out[2*NPAIR] = a[NIN] @ W[NIN][2*NPAIR] + bias, optional ReLU.
// `a` is a register array; `out` may be registers or the per-thread smem
// bounce buffer. Chunked (CP pairs) to bound accumulator pressure.
template<int NIN, int NPAIR, int CP, bool RELU>
__device__ __forceinline__ void gemv(const float* __restrict__ a,
                                     const float* __restrict__ W,
                                     const float* __restrict__ bias,
                                     float* __restrict__ out) {
#pragma unroll
    for (int c0 = 0; c0 < NPAIR; c0 += CP) {
        u64 acc[CP];
        const ulonglong2* bp =
            reinterpret_cast<const ulonglong2*>(bias + 2 * c0);
#pragma unroll
        for (int q = 0; q < CP / 2; q++) {
            ulonglong2 b2 = bp[q];
            acc[2 * q] = b2.x; acc[2 * q + 1] = b2.y;
        }
#pragma unroll
        for (int i = 0; i < NIN; i++) {
            u64 a2 = bcast2(a[i]);
            const ulonglong2* wp =
                reinterpret_cast<const ulonglong2*>(W + i * (2 * NPAIR) + 2 * c0);
#pragma unroll
            for (int q = 0; q < CP / 2; q++) {
                ulonglong2 w2 = wp[q];
                fma2(acc[2 * q],     a2, w2.x);
                fma2(acc[2 * q + 1], a2, w2.y);
            }
        }
#pragma unroll
        for (int p = 0; p < CP; p++) {
            float lo, hi;
            unpack2(acc[p], lo, hi);
            if (RELU) { lo = fmaxf(lo, 0.f); hi = fmaxf(hi, 0.f); }
            out[2 * (c0 + p)] = lo;
            out[2 * (c0 + p) + 1] = hi;
        }
    }
}

__device__ __forceinline__ void load64s(float* __restrict__ dst,
                                        const float* __restrict__ st) {
#pragma unroll
    for (int j = 0; j < 64; j++) dst[j] = st[j];
}

__device__ __forceinline__ void ln_gelu(float* h, const float* __restrict__ g,
                                        const float* __restrict__ b) {
    float m0 = 0.f, m1 = 0.f;
#pragma unroll
    for (int j = 0; j < 64; j += 2) { m0 += h[j]; m1 += h[j + 1]; }
    float mu = (m0 + m1) * (1.f / 64.f);
    float v0 = 0.f, v1 = 0.f;
#pragma unroll
    for (int j = 0; j < 64; j += 2) {
        float d0 = h[j] - mu;      v0 = fmaf(d0, d0, v0);
        float d1 = h[j + 1] - mu;  v1 = fmaf(d1, d1, v1);
    }
    float var = (v0 + v1) * (1.f / 64.f);
    float inv = rsqrtf(var + 1e-5f);
#pragma unroll
    for (int j = 0; j < 64; j++) {
        float v = (h[j] - mu) * inv * g[j] + b[j];
        h[j] = 0.5f * v * (1.f + erff(v * 0.70710678118654752f));
    }
}

// ---------------- rational-quadratic spline (one row) ----------------
__device__ __forceinline__ void rqs_step(const float* __restrict__ p3,
                                         float& z, float& ladj) {
    const float* pw = p3;
    const float* ph = p3 + 8;
    const float* pd = p3 + 16;
    float ew[8], eh[8];
    float mw = pw[0], mh = ph[0];
#pragma unroll
    for (int n = 1; n < 8; n++) {
        mw = fmaxf(mw, pw[n]); mh = fmaxf(mh, ph[n]);
    }
    float sw = 0.f, sh = 0.f;
#pragma unroll
    for (int n = 0; n < 8; n++) {
        ew[n] = __expf(pw[n] - mw); sw += ew[n];
        eh[n] = __expf(ph[n] - mh); sh += eh[n];
    }
    float aw = __fdividef(10.0f, sw), ah = __fdividef(10.0f, sh);
    float xk[9], yk[9], dk[9];
    xk[0] = -5.f; yk[0] = -5.f; dk[0] = 1.f; dk[8] = 1.f;
#pragma unroll
    for (int n = 0; n < 8; n++) {
        xk[n + 1] = fmaf(ew[n], aw, xk[n]);
        yk[n + 1] = fmaf(eh[n], ah, yk[n]);
    }
#pragma unroll
    for (int n = 0; n < 7; n++) {
        float v = pd[n];
        dk[n + 1] = fmaxf(v, 0.f) + log1pf(__expf(-fabsf(v)));
    }
    bool inside = (z > -5.f) && (z < 5.f);
    float xc = fminf(fmaxf(z, -5.f), 5.f);
    float x0 = xk[0], x1 = xk[1], y0 = yk[0], y1 = yk[1];
    float d0 = dk[0], d1 = dk[1];
#pragma unroll
    for (int m = 1; m < 8; m++) {
        bool cc = xc >= xk[m];
        x0 = cc ? xk[m] : x0;     x1 = cc ? xk[m + 1] : x1;
        y0 = cc ? yk[m] : y0;     y1 = cc ? yk[m + 1] : y1;
        d0 = cc ? dk[m] : d0;     d1 = cc ? dk[m + 1] : d1;
    }
    float wk = x1 - x0, hk = y1 - y0;
    float s  = __fdividef(hk, wk);
    float xi = __fdividef(xc - x0, wk);
    float om = 1.f - xi;
    float den = fmaf(fmaf(-2.f, s, d0 + d1), xi * om, s);
    float yin = y0 + hk * __fdividef(s * xi * xi + d0 * xi * om, den);
    float A   = fmaf(d1 * xi, xi, fmaf(2.f * s * xi, om, d0 * om * om));
    float ldin = __logf(__fdividef((s * s) * A, den * den));
    z    = inside ? yin : z;
    ladj = inside ? (ladj + ldin) : ladj;
}

__global__ void nudge_kernel(int) {}

// ======================= encoder =======================
__global__ __launch_bounds__(THREADS, 1)
void encoder_kernel(
    const float* __restrict__ metadata, const float* __restrict__ mask,
    const float* __restrict__ eW1, const float* __restrict__ eb1,
    const float* __restrict__ eg1, const float* __restrict__ ebt1,
    const float* __restrict__ eW2, const float* __restrict__ eb2,
    const float* __restrict__ eg2, const float* __restrict__ ebt2,
    const float* __restrict__ eW3, const float* __restrict__ eb3,
    float* __restrict__ out_latent, int B)
{
    extern __shared__ float sm[];
    const int tid = threadIdx.x;
    for (int idx = tid; idx < 22 * 64; idx += THREADS) sm[EW1 + idx] = eW1[idx];
    for (int idx = tid; idx < 64; idx += THREADS) {
        sm[EB1 + idx] = eb1[idx];  sm[ELN1G + idx] = eg1[idx];
        sm[ELN1B + idx] = ebt1[idx];
        sm[EB2 + idx] = eb2[idx];  sm[ELN2G + idx] = eg2[idx];
        sm[ELN2B + idx] = ebt2[idx];
    }
    for (int idx = tid; idx < 64 * 64; idx += THREADS) sm[EW2 + idx] = eW2[idx];
    for (int idx = tid; idx < 64 * 32; idx += THREADS) sm[EW3 + idx] = eW3[idx];
    for (int idx = tid; idx < 32; idx += THREADS)      sm[EB3 + idx] = eb3[idx];
    __syncthreads();

    float* __restrict__ st = sm + ESTASH + tid * 65;

    for (int row = blockIdx.x * THREADS + tid; row < B;
         row += gridDim.x * THREADS) {
        const size_t rowl = (size_t)row;
        float x[22];
        const float* mr = metadata + rowl * 11;
        const float* kr = mask + rowl * 11;
#pragma unroll
        for (int i = 0; i < 11; i++) x[i] = __ldg(mr + i);
#pragma unroll
        for (int i = 0; i < 11; i++) x[11 + i] = __ldg(kr + i);

        // L1: regs -> stash; reload -> regs; LN+GELU in regs
        gemv<22, 32, 8, false>(x, sm + EW1, sm + EB1, st);
        float h[64];
        load64s(h, st);
        ln_gelu(h, sm + ELN1G, sm + ELN1B);

        // L2: regs -> stash; reload; LN+GELU
        gemv<64, 32, 8, false>(h, sm + EW2, sm + EB2, st);
        float h2[64];
        load64s(h2, st);
        ln_gelu(h2, sm + ELN2G, sm + ELN2B);

        // L3: regs -> regs (only 32 outputs)
        float c[32];
        gemv<64, 16, 8, false>(h2, sm + EW3, sm + EB3, c);
        float4* o = reinterpret_cast<float4*>(out_latent + rowl * 32);
#pragma unroll
        for (int q = 0; q < 8; q++)
            o[q] = make_float4(c[4 * q], c[4 * q + 1],
                               c[4 * q + 2], c[4 * q + 3]);
    }
}

// ======================= one flow transform =======================
__global__ __launch_bounds__(THREADS, 1)
void flow_kernel(
    const float* __restrict__ latent, const float* __restrict__ prot,
    const float* __restrict__ age,
    const float* __restrict__ fW1t, const float* __restrict__ fb1t,
    const float* __restrict__ fW2t, const float* __restrict__ fb2t,
    const float* __restrict__ fW3t, const float* __restrict__ fb3t,
    int first, int B)
{
    extern __shared__ float sm[];
    const int tid = threadIdx.x;
    for (int idx = tid; idx < 33 * 64; idx += THREADS) sm[FW1 + idx] = fW1t[idx];
    for (int idx = tid; idx < 64; idx += THREADS) {
        sm[FB1 + idx] = fb1t[idx];
        sm[FB2 + idx] = fb2t[idx];
    }
    for (int idx = tid; idx < 64 * 64; idx += THREADS) sm[FW2 + idx] = fW2t[idx];
    for (int idx = tid; idx < 64 * 24; idx += THREADS) {
        int i = idx / 24, n = idx % 24;
        sm[FW3 + idx] = (n < 23) ? fW3t[i * 23 + n] : 0.f;
    }
    for (int idx = tid; idx < 24; idx += THREADS)
        sm[FB3 + idx] = (idx < 23) ? fb3t[idx] : 0.f;
    __syncthreads();

    float* __restrict__ st = sm + FSTASH + tid * 65;

    for (int row = blockIdx.x * THREADS + tid; row < B;
         row += gridDim.x * THREADS) {
        const size_t rowl = (size_t)row;

        float ctx[33];
#pragma unroll
        for (int q = 0; q < 8; q++) {
            float4 a = reinterpret_cast<const float4*>(latent + rowl * 32)[q];
            ctx[4 * q] = a.x; ctx[4 * q + 1] = a.y;
            ctx[4 * q + 2] = a.z; ctx[4 * q + 3] = a.w;
        }
        ctx[32] = __ldg(prot + row);

        float z, ladj;
        if (first) { z = __ldg(age + row); ladj = 0.f; }
        else       { z = g_z[row];         ladj = g_ladj[row]; }

        // F1: ctx regs -> stash (ReLU); reload
        gemv<33, 32, 8, true>(ctx, sm + FW1, sm + FB1, st);
        float p1[64];
        load64s(p1, st);

        // F2: regs -> stash (ReLU); reload
        gemv<64, 32, 8, true>(p1, sm + FW2, sm + FB2, st);
        float p2[64];
        load64s(p2, st);

        // F3: regs -> regs (24 outputs)
        float p3[24];
        gemv<64, 12, 6, false>(p2, sm + FW3, sm + FB3, p3);

        rqs_step(p3, z, ladj);

        g_z[row] = z;
        g_ladj[row] = ladj;
    }
}

// ======================= log_prob + reduction =======================
__global__ __launch_bounds__(256, 1)
void lp_kernel(float* __restrict__ out_lp, int B) {
    __shared__ float red[256];
    float lsum = 0.f;
    for (int row = blockIdx.x * 256 + threadIdx.x; row < B;
         row += gridDim.x * 256) {
        float z = g_z[row];
        float lp = fmaf(-0.5f, z * z, -0.91893853320467274f) + g_ladj[row];
        out_lp[row] = lp;
        lsum += lp;
    }
    red[threadIdx.x] = lsum;
    __syncthreads();
#pragma unroll
    for (int off = 128; off > 0; off >>= 1) {
        if (threadIdx.x < off) red[threadIdx.x] += red[threadIdx.x + off];
        __syncthreads();
    }
    if (threadIdx.x == 0) g_block_sums[blockIdx.x] = red[0];
}

__global__ void finalize_kernel(int B, float* __restrict__ out_nll) {
    __shared__ double red[256];
    double s = 0.0;
    for (int i = threadIdx.x; i < LP_BLOCKS; i += 256)
        s += (double)g_block_sums[i];
    red[threadIdx.x] = s;
    __syncthreads();
#pragma unroll
    for (int off = 128; off > 0; off >>= 1) {
        if (threadIdx.x < off) red[threadIdx.x] += red[threadIdx.x + off];
        __syncthreads();
    }
    if (threadIdx.x == 0)
        out_nll[0] = (float)(-red[0] / (double)B);
}

extern "C" void kernel_launch(void* const* d_in, const int* in_sizes, int n_in,
                              void* d_out, int out_size) {
    const float* metadata = (const float*)d_in[0];
    const float* prot     = (const float*)d_in[1];
    const float* age      = (const float*)d_in[2];
    const float* mask     = (const float*)d_in[3];
    const float* eW1  = (const float*)d_in[4];
    const float* eb1  = (const float*)d_in[5];
    const float* eg1  = (const float*)d_in[6];
    const float* ebt1 = (const float*)d_in[7];
    const float* eW2  = (const float*)d_in[8];
    const float* eb2  = (const float*)d_in[9];
    const float* eg2  = (const float*)d_in[10];
    const float* ebt2 = (const float*)d_in[11];
    const float* eW3  = (const float*)d_in[12];
    const float* eb3  = (const float*)d_in[13];
    const float* fW1  = (const float*)d_in[14];
    const float* fb1  = (const float*)d_in[15];
    const float* fW2  = (const float*)d_in[16];
    const float* fb2  = (const float*)d_in[17];
    const float* fW3  = (const float*)d_in[18];
    const float* fb3  = (const float*)d_in[19];

    const int B = in_sizes[1];
    float* out = (float*)d_out;
    float* out_latent = out;
    float* out_lp     = out + (size_t)B * 32;
    float* out_nll    = out + (size_t)B * 33;

    int sms = 148;
    cudaDeviceProp prop;
    if (cudaGetDeviceProperties(&prop, 0) == cudaSuccess)
        sms = prop.multiProcessorCount;

    size_t enc_smem  = (size_t)ENC_SM * sizeof(float);
    size_t flow_smem = (size_t)FLOW_SM * sizeof(float);
    cudaFuncSetAttribute(encoder_kernel,
                         cudaFuncAttributeMaxDynamicSharedMemorySize,
                         (int)enc_smem);
    cudaFuncSetAttribute(flow_kernel,
                         cudaFuncAttributeMaxDynamicSharedMemorySize,
                         (int)flow_smem);

    // launch idx map: 0 nudge, 1 enc, 2 f0, 3 f1, 4 f2, 5 f3 (<- ncu -s 5),
    // 6 lp, 7 finalize
    nudge_kernel<<<1, 32>>>(0);

    encoder_kernel<<<sms, THREADS, enc_smem>>>(
        metadata, mask, eW1, eb1, eg1, ebt1, eW2, eb2, eg2, ebt2, eW3, eb3,
        out_latent, B);

    for (int t = 0; t < 4; t++) {
        flow_kernel<<<sms, THREADS, flow_smem>>>(
            out_latent, prot, age,
            fW1 + (size_t)t * 33 * 64, fb1 + (size_t)t * 64,
            fW2 + (size_t)t * 64 * 64, fb2 + (size_t)t * 64,
            fW3 + (size_t)t * 64 * 23, fb3 + (size_t)t * 23,
            (t == 0) ? 1 : 0, B);
    }

    lp_kernel<<<LP_BLOCKS, 256>>>(out_lp, B);
    finalize_kernel<<<1, 256>>>(B, out_nll);
}